// round 4
// baseline (speedup 1.0000x reference)
#include <cuda_runtime.h>
#include <cstdint>

#define N_NODES 100000
#define N_EDGES 1600000
#define D 128
#define NGRAPH 64
#define DOUT 16
#define LN_EPS 1e-5f
#define SCAN_B 1024
#define SCAN_NB ((N_NODES + SCAN_B - 1) / SCAN_B)   // 98

// ---------------- scratch (static device globals; no allocation) ----------------
__device__ float g_A[N_NODES * D];
__device__ float g_B[N_NODES * D];
__device__ int   g_cnti[N_NODES];
__device__ int   g_offs[N_NODES + 1];
__device__ int   g_cursor[N_NODES];
__device__ int   g_adj[N_EDGES];
__device__ int   g_bsum[SCAN_NB];
__device__ float g_dinv[N_NODES];
__device__ float g_pooled[NGRAPH * D];
__device__ float g_gcnt[NGRAPH];

// ---------------- init ----------------
__global__ void k_init() {
    int i = blockIdx.x * blockDim.x + threadIdx.x;
    if (i < N_NODES) g_cnti[i] = 0;
    if (i < NGRAPH * D) g_pooled[i] = 0.0f;
    if (i < NGRAPH) g_gcnt[i] = 0.0f;
}

__global__ void k_count(const int* __restrict__ dst) {
    int i = blockIdx.x * blockDim.x + threadIdx.x;
    if (i < N_EDGES) atomicAdd(&g_cnti[dst[i]], 1);
}

__global__ void k_dinv() {
    int i = blockIdx.x * blockDim.x + threadIdx.x;
    if (i < N_NODES) g_dinv[i] = rsqrtf((float)(g_cnti[i] + 1));  // +1 self-loop
}

// ---------------- prefix scan ----------------
__global__ void k_scan1() {
    __shared__ int sh[SCAN_B];
    int i = blockIdx.x * SCAN_B + threadIdx.x;
    int v = (i < N_NODES) ? g_cnti[i] : 0;
    sh[threadIdx.x] = v;
    __syncthreads();
#pragma unroll
    for (int o = 1; o < SCAN_B; o <<= 1) {
        int t = (threadIdx.x >= o) ? sh[threadIdx.x - o] : 0;
        __syncthreads();
        sh[threadIdx.x] += t;
        __syncthreads();
    }
    if (i < N_NODES) g_offs[i + 1] = sh[threadIdx.x];
    if (threadIdx.x == SCAN_B - 1) g_bsum[blockIdx.x] = sh[SCAN_B - 1];
}

__global__ void k_scan2() {
    if (threadIdx.x == 0) {
        int run = 0;
        for (int b = 0; b < SCAN_NB; b++) {
            int t = g_bsum[b];
            g_bsum[b] = run;
            run += t;
        }
    }
}

__global__ void k_scan3() {
    int i = blockIdx.x * SCAN_B + threadIdx.x;
    if (i < N_NODES) {
        int incl = g_offs[i + 1] + g_bsum[blockIdx.x];
        g_offs[i + 1] = incl;
        if (i + 1 < N_NODES) g_cursor[i + 1] = incl;
    }
    if (i == 0) { g_offs[0] = 0; g_cursor[0] = 0; }
}

__global__ void k_fill(const int* __restrict__ src, const int* __restrict__ dst) {
    int e = blockIdx.x * blockDim.x + threadIdx.x;
    if (e < N_EDGES) {
        int d = dst[e];
        int pos = atomicAdd(&g_cursor[d], 1);
        g_adj[pos] = src[e];
    }
}

// ---------------- TF32 tensor-core GEMM: C[M,128] = A[M,128] @ W[128,128] ----------------
#define AS_STRIDE 36
#define WS_STRIDE 132

__device__ __forceinline__ uint32_t f2tf32(float f) {
    uint32_t u;
    asm("cvt.rna.tf32.f32 %0, %1;" : "=r"(u) : "f"(f));
    return u;
}

__global__ void __launch_bounds__(256) k_gemm(const float* __restrict__ A,
                                              const float* __restrict__ W,
                                              float* __restrict__ C) {
    __shared__ uint32_t As[128 * AS_STRIDE];
    __shared__ uint32_t Ws[32 * WS_STRIDE];
    int tid = threadIdx.x;
    int lane = tid & 31;
    int w = tid >> 5;
    int warpM = (w >> 1) * 32;
    int warpN = (w & 1) * 64;
    int g = lane >> 2;
    int t = lane & 3;
    int rowBase = blockIdx.x * 128;

    float c[2][8][4];
#pragma unroll
    for (int mi = 0; mi < 2; mi++)
#pragma unroll
        for (int nt = 0; nt < 8; nt++)
#pragma unroll
            for (int q = 0; q < 4; q++) c[mi][nt][q] = 0.f;

    for (int k0 = 0; k0 < 128; k0 += 32) {
#pragma unroll
        for (int i = 0; i < 4; i++) {
            int idx = tid + i * 256;
            int r = idx >> 3;
            int c4 = idx & 7;
            int grow = rowBase + r;
            float4 v = make_float4(0.f, 0.f, 0.f, 0.f);
            if (grow < N_NODES)
                v = *reinterpret_cast<const float4*>(&A[grow * D + k0 + c4 * 4]);
            uint32_t* p = &As[r * AS_STRIDE + c4 * 4];
            p[0] = f2tf32(v.x); p[1] = f2tf32(v.y);
            p[2] = f2tf32(v.z); p[3] = f2tf32(v.w);
        }
#pragma unroll
        for (int i = 0; i < 4; i++) {
            int idx = tid + i * 256;
            int r = idx >> 5;
            int c4 = idx & 31;
            float4 v = *reinterpret_cast<const float4*>(&W[(k0 + r) * D + c4 * 4]);
            uint32_t* p = &Ws[r * WS_STRIDE + c4 * 4];
            p[0] = f2tf32(v.x); p[1] = f2tf32(v.y);
            p[2] = f2tf32(v.z); p[3] = f2tf32(v.w);
        }
        __syncthreads();

#pragma unroll
        for (int kk = 0; kk < 4; kk++) {
            int kb = kk * 8;
            uint32_t af[2][4];
#pragma unroll
            for (int mi = 0; mi < 2; mi++) {
                int r = warpM + mi * 16;
                af[mi][0] = As[(r + g)     * AS_STRIDE + kb + t];
                af[mi][1] = As[(r + g + 8) * AS_STRIDE + kb + t];
                af[mi][2] = As[(r + g)     * AS_STRIDE + kb + t + 4];
                af[mi][3] = As[(r + g + 8) * AS_STRIDE + kb + t + 4];
            }
#pragma unroll
            for (int nt = 0; nt < 8; nt++) {
                int nb = warpN + nt * 8;
                uint32_t b0 = Ws[(kb + t)     * WS_STRIDE + nb + g];
                uint32_t b1 = Ws[(kb + t + 4) * WS_STRIDE + nb + g];
#pragma unroll
                for (int mi = 0; mi < 2; mi++) {
                    asm volatile(
                        "mma.sync.aligned.m16n8k8.row.col.f32.tf32.tf32.f32 "
                        "{%0,%1,%2,%3}, {%4,%5,%6,%7}, {%8,%9}, {%0,%1,%2,%3};"
                        : "+f"(c[mi][nt][0]), "+f"(c[mi][nt][1]),
                          "+f"(c[mi][nt][2]), "+f"(c[mi][nt][3])
                        : "r"(af[mi][0]), "r"(af[mi][1]), "r"(af[mi][2]), "r"(af[mi][3]),
                          "r"(b0), "r"(b1));
                }
            }
        }
        __syncthreads();
    }

#pragma unroll
    for (int mi = 0; mi < 2; mi++) {
#pragma unroll
        for (int nt = 0; nt < 8; nt++) {
            int colBase = warpN + nt * 8 + t * 2;
            int r0 = rowBase + warpM + mi * 16 + g;
            int r1 = r0 + 8;
            if (r0 < N_NODES)
                *reinterpret_cast<float2*>(&C[r0 * D + colBase]) =
                    make_float2(c[mi][nt][0], c[mi][nt][1]);
            if (r1 < N_NODES)
                *reinterpret_cast<float2*>(&C[r1 * D + colBase]) =
                    make_float2(c[mi][nt][2], c[mi][nt][3]);
        }
    }
}

// ---------------- fused gather + self-loop + bias + LN + ReLU ----------------
// One warp per node. Uniform broadcast loads for indices (no shuffles),
// 2 independent accumulator quads for MLP.
__global__ void __launch_bounds__(256) k_gather(const float* __restrict__ h,
                                                const float* __restrict__ bias,
                                                const float* __restrict__ lng,
                                                const float* __restrict__ lnb,
                                                float* __restrict__ out) {
    int node = blockIdx.x * 8 + (threadIdx.x >> 5);
    if (node >= N_NODES) return;
    int lane = threadIdx.x & 31;
    float di = g_dinv[node];
    const float4* __restrict__ h4 = reinterpret_cast<const float4*>(h);
    int base = node * 32 + lane;

    // self-loop term -> accumulator 0
    float4 hv = __ldg(&h4[base]);
    float sc = di * di;
    float a0x = hv.x * sc, a0y = hv.y * sc, a0z = hv.z * sc, a0w = hv.w * sc;
    float a1x = 0.f, a1y = 0.f, a1z = 0.f, a1w = 0.f;

    int j = __ldg(&g_offs[node]);
    int end = __ldg(&g_offs[node + 1]);

#pragma unroll 2
    for (; j + 2 <= end; j += 2) {
        int s0 = __ldg(&g_adj[j]);
        int s1 = __ldg(&g_adj[j + 1]);
        float n0 = __ldg(&g_dinv[s0]) * di;
        float n1 = __ldg(&g_dinv[s1]) * di;
        float4 v0 = __ldg(&h4[s0 * 32 + lane]);
        float4 v1 = __ldg(&h4[s1 * 32 + lane]);
        a0x = fmaf(v0.x, n0, a0x); a1x = fmaf(v1.x, n1, a1x);
        a0y = fmaf(v0.y, n0, a0y); a1y = fmaf(v1.y, n1, a1y);
        a0z = fmaf(v0.z, n0, a0z); a1z = fmaf(v1.z, n1, a1z);
        a0w = fmaf(v0.w, n0, a0w); a1w = fmaf(v1.w, n1, a1w);
    }
    if (j < end) {
        int s0 = __ldg(&g_adj[j]);
        float n0 = __ldg(&g_dinv[s0]) * di;
        float4 v0 = __ldg(&h4[s0 * 32 + lane]);
        a0x = fmaf(v0.x, n0, a0x);
        a0y = fmaf(v0.y, n0, a0y);
        a0z = fmaf(v0.z, n0, a0z);
        a0w = fmaf(v0.w, n0, a0w);
    }

    float4 b4 = __ldg(&reinterpret_cast<const float4*>(bias)[lane]);
    float ax = a0x + a1x + b4.x;
    float ay = a0y + a1y + b4.y;
    float az = a0z + a1z + b4.z;
    float aw = a0w + a1w + b4.w;

    float s = ax + ay + az + aw;
#pragma unroll
    for (int o = 16; o > 0; o >>= 1) s += __shfl_xor_sync(0xFFFFFFFFu, s, o);
    float mu = s * (1.0f / D);
    float dx = ax - mu, dy = ay - mu, dz = az - mu, dw = aw - mu;
    float sq = dx * dx + dy * dy + dz * dz + dw * dw;
#pragma unroll
    for (int o = 16; o > 0; o >>= 1) sq += __shfl_xor_sync(0xFFFFFFFFu, sq, o);
    float rs = rsqrtf(sq * (1.0f / D) + LN_EPS);

    float4 g4 = __ldg(&reinterpret_cast<const float4*>(lng)[lane]);
    float4 p4 = __ldg(&reinterpret_cast<const float4*>(lnb)[lane]);
    float4 o4;
    o4.x = fmaxf(dx * rs * g4.x + p4.x, 0.f);
    o4.y = fmaxf(dy * rs * g4.y + p4.y, 0.f);
    o4.z = fmaxf(dz * rs * g4.z + p4.z, 0.f);
    o4.w = fmaxf(dw * rs * g4.w + p4.w, 0.f);
    reinterpret_cast<float4*>(out)[base] = o4;
}

// ---------------- graph mean pool (batch sorted) ----------------
#define POOL_CHUNK 128
__global__ void __launch_bounds__(128) k_pool(const float* __restrict__ h,
                                              const int* __restrict__ batch) {
    int f = threadIdx.x;
    int start = blockIdx.x * POOL_CHUNK;
    if (start >= N_NODES) return;
    int end = min(start + POOL_CHUNK, N_NODES);
    float sum = 0.f;
    int cur = __ldg(&batch[start]);
    for (int n = start; n < end; n++) {
        int gg = __ldg(&batch[n]);
        if (gg != cur) {
            atomicAdd(&g_pooled[cur * D + f], sum);
            sum = 0.f;
            cur = gg;
        }
        sum += h[n * D + f];
    }
    atomicAdd(&g_pooled[cur * D + f], sum);
}

__global__ void __launch_bounds__(256) k_cnt(const int* __restrict__ batch) {
    __shared__ float hist[NGRAPH];
    if (threadIdx.x < NGRAPH) hist[threadIdx.x] = 0.f;
    __syncthreads();
    for (int n = blockIdx.x * blockDim.x + threadIdx.x; n < N_NODES;
         n += gridDim.x * blockDim.x)
        atomicAdd(&hist[batch[n]], 1.0f);
    __syncthreads();
    if (threadIdx.x < NGRAPH) atomicAdd(&g_gcnt[threadIdx.x], hist[threadIdx.x]);
}

// ---------------- head ----------------
__global__ void __launch_bounds__(1024) k_final(const float* __restrict__ lw,
                                                const float* __restrict__ lb,
                                                float* __restrict__ out) {
    int t = threadIdx.x;
    int g = t >> 4;
    int o = t & 15;
    float acc = 0.f;
#pragma unroll 8
    for (int f = 0; f < D; f++) acc += g_pooled[g * D + f] * __ldg(&lw[f * DOUT + o]);
    out[t] = acc / fmaxf(g_gcnt[g], 1.0f) + __ldg(&lb[o]);
}

// ---------------- launch ----------------
extern "C" void kernel_launch(void* const* d_in, const int* in_sizes, int n_in,
                              void* d_out, int out_size) {
    const float* x     = (const float*)d_in[0];
    const int*   ei    = (const int*)d_in[1];
    const int*   src   = ei;
    const int*   dst   = ei + N_EDGES;
    const int*   batch = (const int*)d_in[2];
    const float* W1    = (const float*)d_in[3];
    const float* b1    = (const float*)d_in[4];
    const float* W2    = (const float*)d_in[5];
    const float* b2    = (const float*)d_in[6];
    const float* lng   = (const float*)d_in[7];
    const float* lnb   = (const float*)d_in[8];
    const float* lw    = (const float*)d_in[9];
    const float* lbias = (const float*)d_in[10];
    float* out = (float*)d_out;

    float *pA = nullptr, *pB = nullptr;
    cudaGetSymbolAddress((void**)&pA, g_A);
    cudaGetSymbolAddress((void**)&pB, g_B);

    const int T = 256;
    // CSR build + degrees
    k_init<<<(N_NODES + T - 1) / T, T>>>();
    k_count<<<(N_EDGES + T - 1) / T, T>>>(dst);
    k_dinv<<<(N_NODES + T - 1) / T, T>>>();
    k_scan1<<<SCAN_NB, SCAN_B>>>();
    k_scan2<<<1, 32>>>();
    k_scan3<<<SCAN_NB, SCAN_B>>>();
    k_fill<<<(N_EDGES + T - 1) / T, T>>>(src, dst);

    // layer 1
    k_gemm<<<(N_NODES + 127) / 128, 256>>>(x, W1, pA);
    k_gather<<<(N_NODES + 7) / 8, 256>>>(pA, b1, lng, lnb, pB);
    // layer 2
    k_gemm<<<(N_NODES + 127) / 128, 256>>>(pB, W2, pA);
    k_gather<<<(N_NODES + 7) / 8, 256>>>(pA, b2, lng, lnb, pB);

    // pool + head
    k_pool<<<(N_NODES + POOL_CHUNK - 1) / POOL_CHUNK, 128>>>(pB, batch);
    k_cnt<<<64, 256>>>(batch);
    k_final<<<1, 1024>>>(lw, lbias, out);
}

// round 5
// speedup vs baseline: 1.1407x; 1.1407x over previous
#include <cuda_runtime.h>
#include <cstdint>

#define N_NODES 100000
#define N_EDGES 1600000
#define D 128
#define NGRAPH 64
#define DOUT 16
#define LN_EPS 1e-5f
#define SCAN_B 1024
#define SCAN_NB ((N_NODES + SCAN_B - 1) / SCAN_B)   // 98

// ---------------- scratch (static device globals; no allocation) ----------------
__device__ float g_A[N_NODES * D];
__device__ float g_B[N_NODES * D];
__device__ int   g_cnti[N_NODES];
__device__ int   g_offs[N_NODES + 1];
__device__ int   g_cursor[N_NODES];
__device__ int   g_adj[N_EDGES];
__device__ int   g_bsum[SCAN_NB];
__device__ float g_dinv[N_NODES];
__device__ float g_pooled[NGRAPH * D];
__device__ float g_gcnt[NGRAPH];

// ---------------- init ----------------
__global__ void k_init() {
    int i = blockIdx.x * blockDim.x + threadIdx.x;
    if (i < N_NODES) g_cnti[i] = 0;
    if (i < NGRAPH * D) g_pooled[i] = 0.0f;
    if (i < NGRAPH) g_gcnt[i] = 0.0f;
}

__global__ void k_count(const int* __restrict__ dst) {
    int i = blockIdx.x * blockDim.x + threadIdx.x;
    if (i < N_EDGES) atomicAdd(&g_cnti[dst[i]], 1);
}

// ---------------- prefix scan (dinv fused into scan1) ----------------
__global__ void k_scan1() {
    __shared__ int sh[SCAN_B];
    int i = blockIdx.x * SCAN_B + threadIdx.x;
    int v = (i < N_NODES) ? g_cnti[i] : 0;
    if (i < N_NODES) g_dinv[i] = rsqrtf((float)(v + 1));   // +1 self-loop
    sh[threadIdx.x] = v;
    __syncthreads();
#pragma unroll
    for (int o = 1; o < SCAN_B; o <<= 1) {
        int t = (threadIdx.x >= o) ? sh[threadIdx.x - o] : 0;
        __syncthreads();
        sh[threadIdx.x] += t;
        __syncthreads();
    }
    if (i < N_NODES) g_offs[i + 1] = sh[threadIdx.x];
    if (threadIdx.x == SCAN_B - 1) g_bsum[blockIdx.x] = sh[SCAN_B - 1];
}

__global__ void k_scan2() {
    if (threadIdx.x == 0) {
        int run = 0;
        for (int b = 0; b < SCAN_NB; b++) {
            int t = g_bsum[b];
            g_bsum[b] = run;
            run += t;
        }
    }
}

__global__ void k_scan3() {
    int i = blockIdx.x * SCAN_B + threadIdx.x;
    if (i < N_NODES) {
        int incl = g_offs[i + 1] + g_bsum[blockIdx.x];
        g_offs[i + 1] = incl;
        if (i + 1 < N_NODES) g_cursor[i + 1] = incl;
    }
    if (i == 0) { g_offs[0] = 0; g_cursor[0] = 0; }
}

__global__ void k_fill(const int* __restrict__ src, const int* __restrict__ dst) {
    int e = blockIdx.x * blockDim.x + threadIdx.x;
    if (e < N_EDGES) {
        int d = dst[e];
        int pos = atomicAdd(&g_cursor[d], 1);
        g_adj[pos] = src[e];
    }
}

// ---------------- TF32 tensor-core GEMM: C[M,128] = A[M,128] @ W[128,128] ----------------
#define AS_STRIDE 36
#define WS_STRIDE 132

__device__ __forceinline__ uint32_t f2tf32(float f) {
    uint32_t u;
    asm("cvt.rna.tf32.f32 %0, %1;" : "=r"(u) : "f"(f));
    return u;
}

__global__ void __launch_bounds__(256) k_gemm(const float* __restrict__ A,
                                              const float* __restrict__ W,
                                              float* __restrict__ C) {
    __shared__ uint32_t As[128 * AS_STRIDE];
    __shared__ uint32_t Ws[32 * WS_STRIDE];
    int tid = threadIdx.x;
    int lane = tid & 31;
    int w = tid >> 5;
    int warpM = (w >> 1) * 32;
    int warpN = (w & 1) * 64;
    int g = lane >> 2;
    int t = lane & 3;
    int rowBase = blockIdx.x * 128;

    float c[2][8][4];
#pragma unroll
    for (int mi = 0; mi < 2; mi++)
#pragma unroll
        for (int nt = 0; nt < 8; nt++)
#pragma unroll
            for (int q = 0; q < 4; q++) c[mi][nt][q] = 0.f;

    for (int k0 = 0; k0 < 128; k0 += 32) {
#pragma unroll
        for (int i = 0; i < 4; i++) {
            int idx = tid + i * 256;
            int r = idx >> 3;
            int c4 = idx & 7;
            int grow = rowBase + r;
            float4 v = make_float4(0.f, 0.f, 0.f, 0.f);
            if (grow < N_NODES)
                v = *reinterpret_cast<const float4*>(&A[grow * D + k0 + c4 * 4]);
            uint32_t* p = &As[r * AS_STRIDE + c4 * 4];
            p[0] = f2tf32(v.x); p[1] = f2tf32(v.y);
            p[2] = f2tf32(v.z); p[3] = f2tf32(v.w);
        }
#pragma unroll
        for (int i = 0; i < 4; i++) {
            int idx = tid + i * 256;
            int r = idx >> 5;
            int c4 = idx & 31;
            float4 v = *reinterpret_cast<const float4*>(&W[(k0 + r) * D + c4 * 4]);
            uint32_t* p = &Ws[r * WS_STRIDE + c4 * 4];
            p[0] = f2tf32(v.x); p[1] = f2tf32(v.y);
            p[2] = f2tf32(v.z); p[3] = f2tf32(v.w);
        }
        __syncthreads();

#pragma unroll
        for (int kk = 0; kk < 4; kk++) {
            int kb = kk * 8;
            uint32_t af[2][4];
#pragma unroll
            for (int mi = 0; mi < 2; mi++) {
                int r = warpM + mi * 16;
                af[mi][0] = As[(r + g)     * AS_STRIDE + kb + t];
                af[mi][1] = As[(r + g + 8) * AS_STRIDE + kb + t];
                af[mi][2] = As[(r + g)     * AS_STRIDE + kb + t + 4];
                af[mi][3] = As[(r + g + 8) * AS_STRIDE + kb + t + 4];
            }
#pragma unroll
            for (int nt = 0; nt < 8; nt++) {
                int nb = warpN + nt * 8;
                uint32_t b0 = Ws[(kb + t)     * WS_STRIDE + nb + g];
                uint32_t b1 = Ws[(kb + t + 4) * WS_STRIDE + nb + g];
#pragma unroll
                for (int mi = 0; mi < 2; mi++) {
                    asm volatile(
                        "mma.sync.aligned.m16n8k8.row.col.f32.tf32.tf32.f32 "
                        "{%0,%1,%2,%3}, {%4,%5,%6,%7}, {%8,%9}, {%0,%1,%2,%3};"
                        : "+f"(c[mi][nt][0]), "+f"(c[mi][nt][1]),
                          "+f"(c[mi][nt][2]), "+f"(c[mi][nt][3])
                        : "r"(af[mi][0]), "r"(af[mi][1]), "r"(af[mi][2]), "r"(af[mi][3]),
                          "r"(b0), "r"(b1));
                }
            }
        }
        __syncthreads();
    }

#pragma unroll
    for (int mi = 0; mi < 2; mi++) {
#pragma unroll
        for (int nt = 0; nt < 8; nt++) {
            int colBase = warpN + nt * 8 + t * 2;
            int r0 = rowBase + warpM + mi * 16 + g;
            int r1 = r0 + 8;
            if (r0 < N_NODES)
                *reinterpret_cast<float2*>(&C[r0 * D + colBase]) =
                    make_float2(c[mi][nt][0], c[mi][nt][1]);
            if (r1 < N_NODES)
                *reinterpret_cast<float2*>(&C[r1 * D + colBase]) =
                    make_float2(c[mi][nt][2], c[mi][nt][3]);
        }
    }
}

// ---------------- fused gather + self-loop + bias + LN + ReLU ----------------
// One warp per node; batched 32-wide index/dinv load + shuffle distribution
// (round-3 structure) with TWO independent accumulator quads for ILP.
__global__ void __launch_bounds__(256) k_gather(const float* __restrict__ h,
                                                const float* __restrict__ bias,
                                                const float* __restrict__ lng,
                                                const float* __restrict__ lnb,
                                                float* __restrict__ out) {
    int node = blockIdx.x * 8 + (threadIdx.x >> 5);
    if (node >= N_NODES) return;
    int lane = threadIdx.x & 31;
    float di = g_dinv[node];
    const float4* __restrict__ h4 = reinterpret_cast<const float4*>(h);
    int base = node * 32 + lane;

    // self-loop term -> accumulator 0
    float4 hv = __ldg(&h4[base]);
    float sc = di * di;
    float a0x = hv.x * sc, a0y = hv.y * sc, a0z = hv.z * sc, a0w = hv.w * sc;
    float a1x = 0.f, a1y = 0.f, a1z = 0.f, a1w = 0.f;

    int beg = __ldg(&g_offs[node]);
    int end = __ldg(&g_offs[node + 1]);
    for (int j0 = beg; j0 < end; j0 += 32) {
        int rem = end - j0;
        int n = rem < 32 ? rem : 32;
        int myidx = 0;
        float mydv = 0.f;
        if (lane < n) {
            myidx = __ldg(&g_adj[j0 + lane]);
            mydv = __ldg(&g_dinv[myidx]);
        }
        int jj = 0;
#pragma unroll 4
        for (; jj + 2 <= n; jj += 2) {
            int s0 = __shfl_sync(0xFFFFFFFFu, myidx, jj);
            int s1 = __shfl_sync(0xFFFFFFFFu, myidx, jj + 1);
            float n0 = __shfl_sync(0xFFFFFFFFu, mydv, jj) * di;
            float n1 = __shfl_sync(0xFFFFFFFFu, mydv, jj + 1) * di;
            float4 v0 = __ldg(&h4[s0 * 32 + lane]);
            float4 v1 = __ldg(&h4[s1 * 32 + lane]);
            a0x = fmaf(v0.x, n0, a0x); a1x = fmaf(v1.x, n1, a1x);
            a0y = fmaf(v0.y, n0, a0y); a1y = fmaf(v1.y, n1, a1y);
            a0z = fmaf(v0.z, n0, a0z); a1z = fmaf(v1.z, n1, a1z);
            a0w = fmaf(v0.w, n0, a0w); a1w = fmaf(v1.w, n1, a1w);
        }
        if (jj < n) {
            int s0 = __shfl_sync(0xFFFFFFFFu, myidx, jj);
            float n0 = __shfl_sync(0xFFFFFFFFu, mydv, jj) * di;
            float4 v0 = __ldg(&h4[s0 * 32 + lane]);
            a0x = fmaf(v0.x, n0, a0x);
            a0y = fmaf(v0.y, n0, a0y);
            a0z = fmaf(v0.z, n0, a0z);
            a0w = fmaf(v0.w, n0, a0w);
        }
    }

    float4 b4 = __ldg(&reinterpret_cast<const float4*>(bias)[lane]);
    float ax = a0x + a1x + b4.x;
    float ay = a0y + a1y + b4.y;
    float az = a0z + a1z + b4.z;
    float aw = a0w + a1w + b4.w;

    float s = ax + ay + az + aw;
#pragma unroll
    for (int o = 16; o > 0; o >>= 1) s += __shfl_xor_sync(0xFFFFFFFFu, s, o);
    float mu = s * (1.0f / D);
    float dx = ax - mu, dy = ay - mu, dz = az - mu, dw = aw - mu;
    float sq = dx * dx + dy * dy + dz * dz + dw * dw;
#pragma unroll
    for (int o = 16; o > 0; o >>= 1) sq += __shfl_xor_sync(0xFFFFFFFFu, sq, o);
    float rs = rsqrtf(sq * (1.0f / D) + LN_EPS);

    float4 g4 = __ldg(&reinterpret_cast<const float4*>(lng)[lane]);
    float4 p4 = __ldg(&reinterpret_cast<const float4*>(lnb)[lane]);
    float4 o4;
    o4.x = fmaxf(dx * rs * g4.x + p4.x, 0.f);
    o4.y = fmaxf(dy * rs * g4.y + p4.y, 0.f);
    o4.z = fmaxf(dz * rs * g4.z + p4.z, 0.f);
    o4.w = fmaxf(dw * rs * g4.w + p4.w, 0.f);
    reinterpret_cast<float4*>(out)[base] = o4;
}

// ---------------- graph mean pool (batch sorted; node-count fused in) ----------------
#define POOL_CHUNK 128
__global__ void __launch_bounds__(128) k_pool(const float* __restrict__ h,
                                              const int* __restrict__ batch) {
    int f = threadIdx.x;
    int start = blockIdx.x * POOL_CHUNK;
    if (start >= N_NODES) return;
    int end = min(start + POOL_CHUNK, N_NODES);
    float sum = 0.f;
    int cnt = 0;
    int cur = __ldg(&batch[start]);
    for (int n = start; n < end; n++) {
        int gg = __ldg(&batch[n]);
        if (gg != cur) {
            atomicAdd(&g_pooled[cur * D + f], sum);
            if (f == 0) atomicAdd(&g_gcnt[cur], (float)cnt);
            sum = 0.f;
            cnt = 0;
            cur = gg;
        }
        sum += h[n * D + f];
        cnt++;
    }
    atomicAdd(&g_pooled[cur * D + f], sum);
    if (f == 0) atomicAdd(&g_gcnt[cur], (float)cnt);
}

// ---------------- head ----------------
__global__ void __launch_bounds__(1024) k_final(const float* __restrict__ lw,
                                                const float* __restrict__ lb,
                                                float* __restrict__ out) {
    int t = threadIdx.x;
    int g = t >> 4;
    int o = t & 15;
    float acc = 0.f;
#pragma unroll 8
    for (int f = 0; f < D; f++) acc += g_pooled[g * D + f] * __ldg(&lw[f * DOUT + o]);
    out[t] = acc / fmaxf(g_gcnt[g], 1.0f) + __ldg(&lb[o]);
}

// ---------------- launch ----------------
extern "C" void kernel_launch(void* const* d_in, const int* in_sizes, int n_in,
                              void* d_out, int out_size) {
    const float* x     = (const float*)d_in[0];
    const int*   ei    = (const int*)d_in[1];
    const int*   src   = ei;
    const int*   dst   = ei + N_EDGES;
    const int*   batch = (const int*)d_in[2];
    const float* W1    = (const float*)d_in[3];
    const float* b1    = (const float*)d_in[4];
    const float* W2    = (const float*)d_in[5];
    const float* b2    = (const float*)d_in[6];
    const float* lng   = (const float*)d_in[7];
    const float* lnb   = (const float*)d_in[8];
    const float* lw    = (const float*)d_in[9];
    const float* lbias = (const float*)d_in[10];
    float* out = (float*)d_out;

    float *pA = nullptr, *pB = nullptr;
    cudaGetSymbolAddress((void**)&pA, g_A);
    cudaGetSymbolAddress((void**)&pB, g_B);

    const int T = 256;
    // CSR build + degrees
    k_init<<<(N_NODES + T - 1) / T, T>>>();
    k_count<<<(N_EDGES + T - 1) / T, T>>>(dst);
    k_scan1<<<SCAN_NB, SCAN_B>>>();
    k_scan2<<<1, 32>>>();
    k_scan3<<<SCAN_NB, SCAN_B>>>();
    k_fill<<<(N_EDGES + T - 1) / T, T>>>(src, dst);

    // layer 1
    k_gemm<<<(N_NODES + 127) / 128, 256>>>(x, W1, pA);
    k_gather<<<(N_NODES + 7) / 8, 256>>>(pA, b1, lng, lnb, pB);
    // layer 2
    k_gemm<<<(N_NODES + 127) / 128, 256>>>(pB, W2, pA);
    k_gather<<<(N_NODES + 7) / 8, 256>>>(pA, b2, lng, lnb, pB);

    // pool + head
    k_pool<<<(N_NODES + POOL_CHUNK - 1) / POOL_CHUNK, 128>>>(pB, batch);
    k_final<<<1, 1024>>>(lw, lbias, out);
}

// round 6
// speedup vs baseline: 1.2154x; 1.0655x over previous
#include <cuda_runtime.h>
#include <cstdint>

#define N_NODES 100000
#define N_EDGES 1600000
#define D 128
#define NGRAPH 64
#define DOUT 16
#define LN_EPS 1e-5f
#define SCAN_B 1024
#define SCAN_NB ((N_NODES + SCAN_B - 1) / SCAN_B)   // 98

// ---------------- scratch (static device globals; no allocation) ----------------
__device__ float g_A[N_NODES * D];
__device__ float g_B[N_NODES * D];
__device__ int   g_cnti[N_NODES];
__device__ int   g_offs[N_NODES + 1];
__device__ int   g_cursor[N_NODES];
__device__ int   g_adj[N_EDGES];
__device__ int   g_bsum[SCAN_NB];
__device__ float g_dinv[N_NODES];
__device__ float g_pooled[NGRAPH * D];
__device__ float g_gcnt[NGRAPH];

// ---------------- init ----------------
__global__ void k_init() {
    int i = blockIdx.x * blockDim.x + threadIdx.x;
    if (i < N_NODES) g_cnti[i] = 0;
    if (i < NGRAPH * D) g_pooled[i] = 0.0f;
    if (i < NGRAPH) g_gcnt[i] = 0.0f;
}

__global__ void k_count(const int* __restrict__ dst) {
    int i = blockIdx.x * blockDim.x + threadIdx.x;
    if (i < N_EDGES) atomicAdd(&g_cnti[dst[i]], 1);
}

// ---------------- prefix scan (dinv fused into scan1) ----------------
__global__ void k_scan1() {
    __shared__ int sh[SCAN_B];
    int i = blockIdx.x * SCAN_B + threadIdx.x;
    int v = (i < N_NODES) ? g_cnti[i] : 0;
    if (i < N_NODES) g_dinv[i] = rsqrtf((float)(v + 1));   // +1 self-loop
    sh[threadIdx.x] = v;
    __syncthreads();
#pragma unroll
    for (int o = 1; o < SCAN_B; o <<= 1) {
        int t = (threadIdx.x >= o) ? sh[threadIdx.x - o] : 0;
        __syncthreads();
        sh[threadIdx.x] += t;
        __syncthreads();
    }
    if (i < N_NODES) g_offs[i + 1] = sh[threadIdx.x];
    if (threadIdx.x == SCAN_B - 1) g_bsum[blockIdx.x] = sh[SCAN_B - 1];
}

// parallel exclusive scan of the 98 block sums (one 128-thread block)
__global__ void k_scan2() {
    __shared__ int sh[128];
    int t = threadIdx.x;
    int v = (t < SCAN_NB) ? g_bsum[t] : 0;
    sh[t] = v;
    __syncthreads();
#pragma unroll
    for (int o = 1; o < 128; o <<= 1) {
        int u = (t >= o) ? sh[t - o] : 0;
        __syncthreads();
        sh[t] += u;
        __syncthreads();
    }
    if (t < SCAN_NB) g_bsum[t] = sh[t] - v;   // exclusive
}

__global__ void k_scan3() {
    int i = blockIdx.x * SCAN_B + threadIdx.x;
    if (i < N_NODES) {
        int incl = g_offs[i + 1] + g_bsum[blockIdx.x];
        g_offs[i + 1] = incl;
        if (i + 1 < N_NODES) g_cursor[i + 1] = incl;
    }
    if (i == 0) { g_offs[0] = 0; g_cursor[0] = 0; }
}

__global__ void k_fill(const int* __restrict__ src, const int* __restrict__ dst) {
    int e = blockIdx.x * blockDim.x + threadIdx.x;
    if (e < N_EDGES) {
        int d = dst[e];
        int pos = atomicAdd(&g_cursor[d], 1);
        g_adj[pos] = src[e];
    }
}

// ---------------- TF32 tensor-core GEMM with dinv-prescaled epilogue ----------------
// C[row] = (A[row] @ W) * dinv[row]
#define AS_STRIDE 36
#define WS_STRIDE 132

__device__ __forceinline__ uint32_t f2tf32(float f) {
    uint32_t u;
    asm("cvt.rna.tf32.f32 %0, %1;" : "=r"(u) : "f"(f));
    return u;
}

__global__ void __launch_bounds__(256) k_gemm(const float* __restrict__ A,
                                              const float* __restrict__ W,
                                              float* __restrict__ C) {
    __shared__ uint32_t As[128 * AS_STRIDE];
    __shared__ uint32_t Ws[32 * WS_STRIDE];
    int tid = threadIdx.x;
    int lane = tid & 31;
    int w = tid >> 5;
    int warpM = (w >> 1) * 32;
    int warpN = (w & 1) * 64;
    int g = lane >> 2;
    int t = lane & 3;
    int rowBase = blockIdx.x * 128;

    float c[2][8][4];
#pragma unroll
    for (int mi = 0; mi < 2; mi++)
#pragma unroll
        for (int nt = 0; nt < 8; nt++)
#pragma unroll
            for (int q = 0; q < 4; q++) c[mi][nt][q] = 0.f;

    for (int k0 = 0; k0 < 128; k0 += 32) {
#pragma unroll
        for (int i = 0; i < 4; i++) {
            int idx = tid + i * 256;
            int r = idx >> 3;
            int c4 = idx & 7;
            int grow = rowBase + r;
            float4 v = make_float4(0.f, 0.f, 0.f, 0.f);
            if (grow < N_NODES)
                v = *reinterpret_cast<const float4*>(&A[grow * D + k0 + c4 * 4]);
            uint32_t* p = &As[r * AS_STRIDE + c4 * 4];
            p[0] = f2tf32(v.x); p[1] = f2tf32(v.y);
            p[2] = f2tf32(v.z); p[3] = f2tf32(v.w);
        }
#pragma unroll
        for (int i = 0; i < 4; i++) {
            int idx = tid + i * 256;
            int r = idx >> 5;
            int c4 = idx & 31;
            float4 v = *reinterpret_cast<const float4*>(&W[(k0 + r) * D + c4 * 4]);
            uint32_t* p = &Ws[r * WS_STRIDE + c4 * 4];
            p[0] = f2tf32(v.x); p[1] = f2tf32(v.y);
            p[2] = f2tf32(v.z); p[3] = f2tf32(v.w);
        }
        __syncthreads();

#pragma unroll
        for (int kk = 0; kk < 4; kk++) {
            int kb = kk * 8;
            uint32_t af[2][4];
#pragma unroll
            for (int mi = 0; mi < 2; mi++) {
                int r = warpM + mi * 16;
                af[mi][0] = As[(r + g)     * AS_STRIDE + kb + t];
                af[mi][1] = As[(r + g + 8) * AS_STRIDE + kb + t];
                af[mi][2] = As[(r + g)     * AS_STRIDE + kb + t + 4];
                af[mi][3] = As[(r + g + 8) * AS_STRIDE + kb + t + 4];
            }
#pragma unroll
            for (int nt = 0; nt < 8; nt++) {
                int nb = warpN + nt * 8;
                uint32_t b0 = Ws[(kb + t)     * WS_STRIDE + nb + g];
                uint32_t b1 = Ws[(kb + t + 4) * WS_STRIDE + nb + g];
#pragma unroll
                for (int mi = 0; mi < 2; mi++) {
                    asm volatile(
                        "mma.sync.aligned.m16n8k8.row.col.f32.tf32.tf32.f32 "
                        "{%0,%1,%2,%3}, {%4,%5,%6,%7}, {%8,%9}, {%0,%1,%2,%3};"
                        : "+f"(c[mi][nt][0]), "+f"(c[mi][nt][1]),
                          "+f"(c[mi][nt][2]), "+f"(c[mi][nt][3])
                        : "r"(af[mi][0]), "r"(af[mi][1]), "r"(af[mi][2]), "r"(af[mi][3]),
                          "r"(b0), "r"(b1));
                }
            }
        }
        __syncthreads();
    }

#pragma unroll
    for (int mi = 0; mi < 2; mi++) {
        int r0 = rowBase + warpM + mi * 16 + g;
        int r1 = r0 + 8;
        float d0 = (r0 < N_NODES) ? __ldg(&g_dinv[r0]) : 0.f;
        float d1 = (r1 < N_NODES) ? __ldg(&g_dinv[r1]) : 0.f;
#pragma unroll
        for (int nt = 0; nt < 8; nt++) {
            int colBase = warpN + nt * 8 + t * 2;
            if (r0 < N_NODES)
                *reinterpret_cast<float2*>(&C[r0 * D + colBase]) =
                    make_float2(c[mi][nt][0] * d0, c[mi][nt][1] * d0);
            if (r1 < N_NODES)
                *reinterpret_cast<float2*>(&C[r1 * D + colBase]) =
                    make_float2(c[mi][nt][2] * d1, c[mi][nt][3] * d1);
        }
    }
}

// ---------------- fused gather + self-loop + bias + LN + ReLU ----------------
// h is pre-scaled by dinv. out = relu(LN(dinv[node]*(h[node] + sum_nbr h[s]) + b))
__global__ void __launch_bounds__(256) k_gather(const float* __restrict__ h,
                                                const float* __restrict__ bias,
                                                const float* __restrict__ lng,
                                                const float* __restrict__ lnb,
                                                float* __restrict__ out) {
    int node = blockIdx.x * 8 + (threadIdx.x >> 5);
    if (node >= N_NODES) return;
    int lane = threadIdx.x & 31;
    float di = g_dinv[node];
    const float4* __restrict__ h4 = reinterpret_cast<const float4*>(h);
    int base = node * 32 + lane;

    // self term (h already scaled by dinv[node])
    float4 hv = __ldg(&h4[base]);
    float a0x = hv.x, a0y = hv.y, a0z = hv.z, a0w = hv.w;
    float a1x = 0.f, a1y = 0.f, a1z = 0.f, a1w = 0.f;

    int beg = __ldg(&g_offs[node]);
    int end = __ldg(&g_offs[node + 1]);
    for (int j0 = beg; j0 < end; j0 += 32) {
        int rem = end - j0;
        int n = rem < 32 ? rem : 32;
        int myidx = 0;
        if (lane < n) myidx = __ldg(&g_adj[j0 + lane]);
        int jj = 0;
#pragma unroll 4
        for (; jj + 2 <= n; jj += 2) {
            int s0 = __shfl_sync(0xFFFFFFFFu, myidx, jj);
            int s1 = __shfl_sync(0xFFFFFFFFu, myidx, jj + 1);
            float4 v0 = __ldg(&h4[s0 * 32 + lane]);
            float4 v1 = __ldg(&h4[s1 * 32 + lane]);
            a0x += v0.x; a1x += v1.x;
            a0y += v0.y; a1y += v1.y;
            a0z += v0.z; a1z += v1.z;
            a0w += v0.w; a1w += v1.w;
        }
        if (jj < n) {
            int s0 = __shfl_sync(0xFFFFFFFFu, myidx, jj);
            float4 v0 = __ldg(&h4[s0 * 32 + lane]);
            a0x += v0.x; a0y += v0.y; a0z += v0.z; a0w += v0.w;
        }
    }

    float4 b4 = __ldg(&reinterpret_cast<const float4*>(bias)[lane]);
    float ax = (a0x + a1x) * di + b4.x;
    float ay = (a0y + a1y) * di + b4.y;
    float az = (a0z + a1z) * di + b4.z;
    float aw = (a0w + a1w) * di + b4.w;

    float s = ax + ay + az + aw;
#pragma unroll
    for (int o = 16; o > 0; o >>= 1) s += __shfl_xor_sync(0xFFFFFFFFu, s, o);
    float mu = s * (1.0f / D);
    float dx = ax - mu, dy = ay - mu, dz = az - mu, dw = aw - mu;
    float sq = dx * dx + dy * dy + dz * dz + dw * dw;
#pragma unroll
    for (int o = 16; o > 0; o >>= 1) sq += __shfl_xor_sync(0xFFFFFFFFu, sq, o);
    float rs = rsqrtf(sq * (1.0f / D) + LN_EPS);

    float4 g4 = __ldg(&reinterpret_cast<const float4*>(lng)[lane]);
    float4 p4 = __ldg(&reinterpret_cast<const float4*>(lnb)[lane]);
    float4 o4;
    o4.x = fmaxf(dx * rs * g4.x + p4.x, 0.f);
    o4.y = fmaxf(dy * rs * g4.y + p4.y, 0.f);
    o4.z = fmaxf(dz * rs * g4.z + p4.z, 0.f);
    o4.w = fmaxf(dw * rs * g4.w + p4.w, 0.f);
    reinterpret_cast<float4*>(out)[base] = o4;
}

// ---------------- graph mean pool (batch sorted; node-count fused in) ----------------
#define POOL_CHUNK 128
__global__ void __launch_bounds__(128) k_pool(const float* __restrict__ h,
                                              const int* __restrict__ batch) {
    int f = threadIdx.x;
    int start = blockIdx.x * POOL_CHUNK;
    if (start >= N_NODES) return;
    int end = min(start + POOL_CHUNK, N_NODES);
    float sum = 0.f;
    int cnt = 0;
    int cur = __ldg(&batch[start]);
    for (int n = start; n < end; n++) {
        int gg = __ldg(&batch[n]);
        if (gg != cur) {
            atomicAdd(&g_pooled[cur * D + f], sum);
            if (f == 0) atomicAdd(&g_gcnt[cur], (float)cnt);
            sum = 0.f;
            cnt = 0;
            cur = gg;
        }
        sum += h[n * D + f];
        cnt++;
    }
    atomicAdd(&g_pooled[cur * D + f], sum);
    if (f == 0) atomicAdd(&g_gcnt[cur], (float)cnt);
}

// ---------------- head ----------------
__global__ void __launch_bounds__(1024) k_final(const float* __restrict__ lw,
                                                const float* __restrict__ lb,
                                                float* __restrict__ out) {
    int t = threadIdx.x;
    int g = t >> 4;
    int o = t & 15;
    float acc = 0.f;
#pragma unroll 8
    for (int f = 0; f < D; f++) acc += g_pooled[g * D + f] * __ldg(&lw[f * DOUT + o]);
    out[t] = acc / fmaxf(g_gcnt[g], 1.0f) + __ldg(&lb[o]);
}

// ---------------- launch ----------------
extern "C" void kernel_launch(void* const* d_in, const int* in_sizes, int n_in,
                              void* d_out, int out_size) {
    const float* x     = (const float*)d_in[0];
    const int*   ei    = (const int*)d_in[1];
    const int*   src   = ei;
    const int*   dst   = ei + N_EDGES;
    const int*   batch = (const int*)d_in[2];
    const float* W1    = (const float*)d_in[3];
    const float* b1    = (const float*)d_in[4];
    const float* W2    = (const float*)d_in[5];
    const float* b2    = (const float*)d_in[6];
    const float* lng   = (const float*)d_in[7];
    const float* lnb   = (const float*)d_in[8];
    const float* lw    = (const float*)d_in[9];
    const float* lbias = (const float*)d_in[10];
    float* out = (float*)d_out;

    float *pA = nullptr, *pB = nullptr;
    cudaGetSymbolAddress((void**)&pA, g_A);
    cudaGetSymbolAddress((void**)&pB, g_B);

    const int T = 256;
    // CSR build + degrees (dinv needed by GEMM epilogue)
    k_init<<<(N_NODES + T - 1) / T, T>>>();
    k_count<<<(N_EDGES + T - 1) / T, T>>>(dst);
    k_scan1<<<SCAN_NB, SCAN_B>>>();
    k_scan2<<<1, 128>>>();
    k_scan3<<<SCAN_NB, SCAN_B>>>();
    k_fill<<<(N_EDGES + T - 1) / T, T>>>(src, dst);

    // layer 1
    k_gemm<<<(N_NODES + 127) / 128, 256>>>(x, W1, pA);
    k_gather<<<(N_NODES + 7) / 8, 256>>>(pA, b1, lng, lnb, pB);
    // layer 2
    k_gemm<<<(N_NODES + 127) / 128, 256>>>(pB, W2, pA);
    k_gather<<<(N_NODES + 7) / 8, 256>>>(pA, b2, lng, lnb, pB);

    // pool + head
    k_pool<<<(N_NODES + POOL_CHUNK - 1) / POOL_CHUNK, 128>>>(pB, batch);
    k_final<<<1, 1024>>>(lw, lbias, out);
}

// round 7
// speedup vs baseline: 1.3773x; 1.1332x over previous
#include <cuda_runtime.h>
#include <cuda_fp16.h>
#include <cstdint>

#define N_NODES 100000
#define N_EDGES 1600000
#define D 128
#define NGRAPH 64
#define DOUT 16
#define LN_EPS 1e-5f
#define SCAN_B 1024
#define SCAN_NB ((N_NODES + SCAN_B - 1) / SCAN_B)   // 98

// ---------------- scratch (static device globals; no allocation) ----------------
__device__ __half g_Ah[N_NODES * D];     // GEMM output, dinv-prescaled, fp16
__device__ float  g_B[N_NODES * D];      // LN output (fp32) / GEMM input
__device__ int    g_cnti[N_NODES];
__device__ int    g_offs[N_NODES + 1];
__device__ int    g_cursor[N_NODES];
__device__ int    g_adj[N_EDGES];
__device__ int    g_bsum[SCAN_NB];
__device__ float  g_dinv[N_NODES];
__device__ float  g_pooled[NGRAPH * D];
__device__ float  g_gcnt[NGRAPH];

// ---------------- init ----------------
__global__ void k_init() {
    int i = blockIdx.x * blockDim.x + threadIdx.x;
    if (i < N_NODES) g_cnti[i] = 0;
    if (i < NGRAPH * D) g_pooled[i] = 0.0f;
    if (i < NGRAPH) g_gcnt[i] = 0.0f;
}

__global__ void k_count(const int* __restrict__ dst) {
    int i = blockIdx.x * blockDim.x + threadIdx.x;
    if (i < N_EDGES) atomicAdd(&g_cnti[dst[i]], 1);
}

// ---------------- prefix scan (dinv fused into scan1) ----------------
__global__ void k_scan1() {
    __shared__ int sh[SCAN_B];
    int i = blockIdx.x * SCAN_B + threadIdx.x;
    int v = (i < N_NODES) ? g_cnti[i] : 0;
    if (i < N_NODES) g_dinv[i] = rsqrtf((float)(v + 1));   // +1 self-loop
    sh[threadIdx.x] = v;
    __syncthreads();
#pragma unroll
    for (int o = 1; o < SCAN_B; o <<= 1) {
        int t = (threadIdx.x >= o) ? sh[threadIdx.x - o] : 0;
        __syncthreads();
        sh[threadIdx.x] += t;
        __syncthreads();
    }
    if (i < N_NODES) g_offs[i + 1] = sh[threadIdx.x];
    if (threadIdx.x == SCAN_B - 1) g_bsum[blockIdx.x] = sh[SCAN_B - 1];
}

__global__ void k_scan2() {
    __shared__ int sh[128];
    int t = threadIdx.x;
    int v = (t < SCAN_NB) ? g_bsum[t] : 0;
    sh[t] = v;
    __syncthreads();
#pragma unroll
    for (int o = 1; o < 128; o <<= 1) {
        int u = (t >= o) ? sh[t - o] : 0;
        __syncthreads();
        sh[t] += u;
        __syncthreads();
    }
    if (t < SCAN_NB) g_bsum[t] = sh[t] - v;   // exclusive
}

__global__ void k_scan3() {
    int i = blockIdx.x * SCAN_B + threadIdx.x;
    if (i < N_NODES) {
        int incl = g_offs[i + 1] + g_bsum[blockIdx.x];
        g_offs[i + 1] = incl;
        if (i + 1 < N_NODES) g_cursor[i + 1] = incl;
    }
    if (i == 0) { g_offs[0] = 0; g_cursor[0] = 0; }
}

__global__ void k_fill(const int* __restrict__ src, const int* __restrict__ dst) {
    int e = blockIdx.x * blockDim.x + threadIdx.x;
    if (e < N_EDGES) {
        int d = dst[e];
        int pos = atomicAdd(&g_cursor[d], 1);
        g_adj[pos] = src[e];
    }
}

// ---------------- TF32 tensor-core GEMM, dinv-prescaled fp16 epilogue ----------------
// Ch[row] = fp16( (A[row] @ W) * dinv[row] )
#define AS_STRIDE 36
#define WS_STRIDE 132

__device__ __forceinline__ uint32_t f2tf32(float f) {
    uint32_t u;
    asm("cvt.rna.tf32.f32 %0, %1;" : "=r"(u) : "f"(f));
    return u;
}

__global__ void __launch_bounds__(256) k_gemm(const float* __restrict__ A,
                                              const float* __restrict__ W,
                                              __half* __restrict__ Ch) {
    __shared__ uint32_t As[128 * AS_STRIDE];
    __shared__ uint32_t Ws[32 * WS_STRIDE];
    int tid = threadIdx.x;
    int lane = tid & 31;
    int w = tid >> 5;
    int warpM = (w >> 1) * 32;
    int warpN = (w & 1) * 64;
    int g = lane >> 2;
    int t = lane & 3;
    int rowBase = blockIdx.x * 128;

    float c[2][8][4];
#pragma unroll
    for (int mi = 0; mi < 2; mi++)
#pragma unroll
        for (int nt = 0; nt < 8; nt++)
#pragma unroll
            for (int q = 0; q < 4; q++) c[mi][nt][q] = 0.f;

    for (int k0 = 0; k0 < 128; k0 += 32) {
#pragma unroll
        for (int i = 0; i < 4; i++) {
            int idx = tid + i * 256;
            int r = idx >> 3;
            int c4 = idx & 7;
            int grow = rowBase + r;
            float4 v = make_float4(0.f, 0.f, 0.f, 0.f);
            if (grow < N_NODES)
                v = *reinterpret_cast<const float4*>(&A[grow * D + k0 + c4 * 4]);
            uint32_t* p = &As[r * AS_STRIDE + c4 * 4];
            p[0] = f2tf32(v.x); p[1] = f2tf32(v.y);
            p[2] = f2tf32(v.z); p[3] = f2tf32(v.w);
        }
#pragma unroll
        for (int i = 0; i < 4; i++) {
            int idx = tid + i * 256;
            int r = idx >> 5;
            int c4 = idx & 31;
            float4 v = *reinterpret_cast<const float4*>(&W[(k0 + r) * D + c4 * 4]);
            uint32_t* p = &Ws[r * WS_STRIDE + c4 * 4];
            p[0] = f2tf32(v.x); p[1] = f2tf32(v.y);
            p[2] = f2tf32(v.z); p[3] = f2tf32(v.w);
        }
        __syncthreads();

#pragma unroll
        for (int kk = 0; kk < 4; kk++) {
            int kb = kk * 8;
            uint32_t af[2][4];
#pragma unroll
            for (int mi = 0; mi < 2; mi++) {
                int r = warpM + mi * 16;
                af[mi][0] = As[(r + g)     * AS_STRIDE + kb + t];
                af[mi][1] = As[(r + g + 8) * AS_STRIDE + kb + t];
                af[mi][2] = As[(r + g)     * AS_STRIDE + kb + t + 4];
                af[mi][3] = As[(r + g + 8) * AS_STRIDE + kb + t + 4];
            }
#pragma unroll
            for (int nt = 0; nt < 8; nt++) {
                int nb = warpN + nt * 8;
                uint32_t b0 = Ws[(kb + t)     * WS_STRIDE + nb + g];
                uint32_t b1 = Ws[(kb + t + 4) * WS_STRIDE + nb + g];
#pragma unroll
                for (int mi = 0; mi < 2; mi++) {
                    asm volatile(
                        "mma.sync.aligned.m16n8k8.row.col.f32.tf32.tf32.f32 "
                        "{%0,%1,%2,%3}, {%4,%5,%6,%7}, {%8,%9}, {%0,%1,%2,%3};"
                        : "+f"(c[mi][nt][0]), "+f"(c[mi][nt][1]),
                          "+f"(c[mi][nt][2]), "+f"(c[mi][nt][3])
                        : "r"(af[mi][0]), "r"(af[mi][1]), "r"(af[mi][2]), "r"(af[mi][3]),
                          "r"(b0), "r"(b1));
                }
            }
        }
        __syncthreads();
    }

    __half2* Ch2 = reinterpret_cast<__half2*>(Ch);
#pragma unroll
    for (int mi = 0; mi < 2; mi++) {
        int r0 = rowBase + warpM + mi * 16 + g;
        int r1 = r0 + 8;
        float d0 = (r0 < N_NODES) ? __ldg(&g_dinv[r0]) : 0.f;
        float d1 = (r1 < N_NODES) ? __ldg(&g_dinv[r1]) : 0.f;
#pragma unroll
        for (int nt = 0; nt < 8; nt++) {
            int colBase = warpN + nt * 8 + t * 2;     // even
            if (r0 < N_NODES)
                Ch2[r0 * 64 + (colBase >> 1)] =
                    __floats2half2_rn(c[mi][nt][0] * d0, c[mi][nt][1] * d0);
            if (r1 < N_NODES)
                Ch2[r1 * 64 + (colBase >> 1)] =
                    __floats2half2_rn(c[mi][nt][2] * d1, c[mi][nt][3] * d1);
        }
    }
}

// ---------------- fused gather + self-loop + bias + LN + ReLU ----------------
// h (fp16) is pre-scaled by dinv. out = relu(LN(dinv[node]*(h[node] + sum_nbr h[s]) + b))
__global__ void __launch_bounds__(256) k_gather(const __half* __restrict__ h,
                                                const float* __restrict__ bias,
                                                const float* __restrict__ lng,
                                                const float* __restrict__ lnb,
                                                float* __restrict__ out) {
    int node = blockIdx.x * 8 + (threadIdx.x >> 5);
    if (node >= N_NODES) return;
    int lane = threadIdx.x & 31;
    float di = g_dinv[node];
    const uint2* __restrict__ hu = reinterpret_cast<const uint2*>(h);  // 4 halfs per elem
    int base = node * 32 + lane;

    // self term (h already scaled by dinv[node])
    uint2 su = __ldg(&hu[base]);
    float2 sf0 = __half22float2(*reinterpret_cast<__half2*>(&su.x));
    float2 sf1 = __half22float2(*reinterpret_cast<__half2*>(&su.y));
    float a0x = sf0.x, a0y = sf0.y, a0z = sf1.x, a0w = sf1.y;
    float a1x = 0.f, a1y = 0.f, a1z = 0.f, a1w = 0.f;

    int beg = __ldg(&g_offs[node]);
    int end = __ldg(&g_offs[node + 1]);
    for (int j0 = beg; j0 < end; j0 += 32) {
        int rem = end - j0;
        int n = rem < 32 ? rem : 32;
        int myidx = 0;
        if (lane < n) myidx = __ldg(&g_adj[j0 + lane]);
        int jj = 0;
#pragma unroll 4
        for (; jj + 2 <= n; jj += 2) {
            int s0 = __shfl_sync(0xFFFFFFFFu, myidx, jj);
            int s1 = __shfl_sync(0xFFFFFFFFu, myidx, jj + 1);
            uint2 u0 = __ldg(&hu[s0 * 32 + lane]);
            uint2 u1 = __ldg(&hu[s1 * 32 + lane]);
            float2 f00 = __half22float2(*reinterpret_cast<__half2*>(&u0.x));
            float2 f01 = __half22float2(*reinterpret_cast<__half2*>(&u0.y));
            float2 f10 = __half22float2(*reinterpret_cast<__half2*>(&u1.x));
            float2 f11 = __half22float2(*reinterpret_cast<__half2*>(&u1.y));
            a0x += f00.x; a1x += f10.x;
            a0y += f00.y; a1y += f10.y;
            a0z += f01.x; a1z += f11.x;
            a0w += f01.y; a1w += f11.y;
        }
        if (jj < n) {
            int s0 = __shfl_sync(0xFFFFFFFFu, myidx, jj);
            uint2 u0 = __ldg(&hu[s0 * 32 + lane]);
            float2 f00 = __half22float2(*reinterpret_cast<__half2*>(&u0.x));
            float2 f01 = __half22float2(*reinterpret_cast<__half2*>(&u0.y));
            a0x += f00.x; a0y += f00.y; a0z += f01.x; a0w += f01.y;
        }
    }

    float4 b4 = __ldg(&reinterpret_cast<const float4*>(bias)[lane]);
    float ax = (a0x + a1x) * di + b4.x;
    float ay = (a0y + a1y) * di + b4.y;
    float az = (a0z + a1z) * di + b4.z;
    float aw = (a0w + a1w) * di + b4.w;

    float s = ax + ay + az + aw;
#pragma unroll
    for (int o = 16; o > 0; o >>= 1) s += __shfl_xor_sync(0xFFFFFFFFu, s, o);
    float mu = s * (1.0f / D);
    float dx = ax - mu, dy = ay - mu, dz = az - mu, dw = aw - mu;
    float sq = dx * dx + dy * dy + dz * dz + dw * dw;
#pragma unroll
    for (int o = 16; o > 0; o >>= 1) sq += __shfl_xor_sync(0xFFFFFFFFu, sq, o);
    float rs = rsqrtf(sq * (1.0f / D) + LN_EPS);

    float4 g4 = __ldg(&reinterpret_cast<const float4*>(lng)[lane]);
    float4 p4 = __ldg(&reinterpret_cast<const float4*>(lnb)[lane]);
    float4 o4;
    o4.x = fmaxf(dx * rs * g4.x + p4.x, 0.f);
    o4.y = fmaxf(dy * rs * g4.y + p4.y, 0.f);
    o4.z = fmaxf(dz * rs * g4.z + p4.z, 0.f);
    o4.w = fmaxf(dw * rs * g4.w + p4.w, 0.f);
    reinterpret_cast<float4*>(out)[node * 32 + lane] = o4;
}

// ---------------- graph mean pool (batch sorted; node-count fused in) ----------------
#define POOL_CHUNK 128
__global__ void __launch_bounds__(128) k_pool(const float* __restrict__ h,
                                              const int* __restrict__ batch) {
    int f = threadIdx.x;
    int start = blockIdx.x * POOL_CHUNK;
    if (start >= N_NODES) return;
    int end = min(start + POOL_CHUNK, N_NODES);
    float sum = 0.f;
    int cnt = 0;
    int cur = __ldg(&batch[start]);
    for (int n = start; n < end; n++) {
        int gg = __ldg(&batch[n]);
        if (gg != cur) {
            atomicAdd(&g_pooled[cur * D + f], sum);
            if (f == 0) atomicAdd(&g_gcnt[cur], (float)cnt);
            sum = 0.f;
            cnt = 0;
            cur = gg;
        }
        sum += h[n * D + f];
        cnt++;
    }
    atomicAdd(&g_pooled[cur * D + f], sum);
    if (f == 0) atomicAdd(&g_gcnt[cur], (float)cnt);
}

// ---------------- head ----------------
__global__ void __launch_bounds__(1024) k_final(const float* __restrict__ lw,
                                                const float* __restrict__ lb,
                                                float* __restrict__ out) {
    int t = threadIdx.x;
    int g = t >> 4;
    int o = t & 15;
    float acc = 0.f;
#pragma unroll 8
    for (int f = 0; f < D; f++) acc += g_pooled[g * D + f] * __ldg(&lw[f * DOUT + o]);
    out[t] = acc / fmaxf(g_gcnt[g], 1.0f) + __ldg(&lb[o]);
}

// ---------------- launch ----------------
extern "C" void kernel_launch(void* const* d_in, const int* in_sizes, int n_in,
                              void* d_out, int out_size) {
    const float* x     = (const float*)d_in[0];
    const int*   ei    = (const int*)d_in[1];
    const int*   src   = ei;
    const int*   dst   = ei + N_EDGES;
    const int*   batch = (const int*)d_in[2];
    const float* W1    = (const float*)d_in[3];
    const float* b1    = (const float*)d_in[4];
    const float* W2    = (const float*)d_in[5];
    const float* b2    = (const float*)d_in[6];
    const float* lng   = (const float*)d_in[7];
    const float* lnb   = (const float*)d_in[8];
    const float* lw    = (const float*)d_in[9];
    const float* lbias = (const float*)d_in[10];
    float* out = (float*)d_out;

    __half* pAh = nullptr;
    float*  pB  = nullptr;
    cudaGetSymbolAddress((void**)&pAh, g_Ah);
    cudaGetSymbolAddress((void**)&pB, g_B);

    const int T = 256;
    // CSR build + degrees (dinv needed by GEMM epilogue)
    k_init<<<(N_NODES + T - 1) / T, T>>>();
    k_count<<<(N_EDGES + T - 1) / T, T>>>(dst);
    k_scan1<<<SCAN_NB, SCAN_B>>>();
    k_scan2<<<1, 128>>>();
    k_scan3<<<SCAN_NB, SCAN_B>>>();
    k_fill<<<(N_EDGES + T - 1) / T, T>>>(src, dst);

    // layer 1
    k_gemm<<<(N_NODES + 127) / 128, 256>>>(x, W1, pAh);
    k_gather<<<(N_NODES + 7) / 8, 256>>>(pAh, b1, lng, lnb, pB);
    // layer 2
    k_gemm<<<(N_NODES + 127) / 128, 256>>>(pB, W2, pAh);
    k_gather<<<(N_NODES + 7) / 8, 256>>>(pAh, b2, lng, lnb, pB);

    // pool + head
    k_pool<<<(N_NODES + POOL_CHUNK - 1) / POOL_CHUNK, 128>>>(pB, batch);
    k_final<<<1, 1024>>>(lw, lbias, out);
}

// round 8
// speedup vs baseline: 1.4526x; 1.0547x over previous
#include <cuda_runtime.h>
#include <cuda_fp16.h>
#include <cstdint>

#define N_NODES 100000
#define N_EDGES 1600000
#define D 128
#define NGRAPH 64
#define DOUT 16
#define LN_EPS 1e-5f
#define SCAN_B 1024
#define SCAN_NB ((N_NODES + SCAN_B - 1) / SCAN_B)   // 98

// ---------------- scratch (static device globals; no allocation) ----------------
__device__ __half g_Ah[N_NODES * D];     // GEMM output, dinv-prescaled, fp16
__device__ float  g_B[N_NODES * D];      // LN output (fp32) / GEMM input
__device__ int    g_cnti[N_NODES];
__device__ int    g_offs[N_NODES + 1];
__device__ int    g_cursor[N_NODES];
__device__ int    g_adj[N_EDGES];
__device__ int    g_bsum[SCAN_NB];
__device__ float  g_dinv[N_NODES];
__device__ float  g_pooled[NGRAPH * D];
__device__ float  g_gcnt[NGRAPH];

// ---------------- init ----------------
__global__ void k_init() {
    int i = blockIdx.x * blockDim.x + threadIdx.x;
    if (i < N_NODES) g_cnti[i] = 0;
    if (i < NGRAPH * D) g_pooled[i] = 0.0f;
    if (i < NGRAPH) g_gcnt[i] = 0.0f;
}

__global__ void k_count(const int* __restrict__ dst) {
    int i = blockIdx.x * blockDim.x + threadIdx.x;
    if (i < N_EDGES) atomicAdd(&g_cnti[dst[i]], 1);
}

__global__ void k_dinv() {
    int i = blockIdx.x * blockDim.x + threadIdx.x;
    if (i < N_NODES) g_dinv[i] = rsqrtf((float)(g_cnti[i] + 1));  // +1 self-loop
}

// ---------------- prefix scan ----------------
__global__ void k_scan1() {
    __shared__ int sh[SCAN_B];
    int i = blockIdx.x * SCAN_B + threadIdx.x;
    int v = (i < N_NODES) ? g_cnti[i] : 0;
    sh[threadIdx.x] = v;
    __syncthreads();
#pragma unroll
    for (int o = 1; o < SCAN_B; o <<= 1) {
        int t = (threadIdx.x >= o) ? sh[threadIdx.x - o] : 0;
        __syncthreads();
        sh[threadIdx.x] += t;
        __syncthreads();
    }
    if (i < N_NODES) g_offs[i + 1] = sh[threadIdx.x];
    if (threadIdx.x == SCAN_B - 1) g_bsum[blockIdx.x] = sh[SCAN_B - 1];
}

__global__ void k_scan2() {
    __shared__ int sh[128];
    int t = threadIdx.x;
    int v = (t < SCAN_NB) ? g_bsum[t] : 0;
    sh[t] = v;
    __syncthreads();
#pragma unroll
    for (int o = 1; o < 128; o <<= 1) {
        int u = (t >= o) ? sh[t - o] : 0;
        __syncthreads();
        sh[t] += u;
        __syncthreads();
    }
    if (t < SCAN_NB) g_bsum[t] = sh[t] - v;   // exclusive
}

__global__ void k_scan3() {
    int i = blockIdx.x * SCAN_B + threadIdx.x;
    if (i < N_NODES) {
        int incl = g_offs[i + 1] + g_bsum[blockIdx.x];
        g_offs[i + 1] = incl;
        if (i + 1 < N_NODES) g_cursor[i + 1] = incl;
    }
    if (i == 0) { g_offs[0] = 0; g_cursor[0] = 0; }
}

__global__ void k_fill(const int* __restrict__ src, const int* __restrict__ dst) {
    int e = blockIdx.x * blockDim.x + threadIdx.x;
    if (e < N_EDGES) {
        int d = dst[e];
        int pos = atomicAdd(&g_cursor[d], 1);
        g_adj[pos] = src[e];
    }
}

// ---------------- TF32 tensor-core GEMM, dinv-prescaled fp16 epilogue ----------------
#define AS_STRIDE 36
#define WS_STRIDE 132

__device__ __forceinline__ uint32_t f2tf32(float f) {
    uint32_t u;
    asm("cvt.rna.tf32.f32 %0, %1;" : "=r"(u) : "f"(f));
    return u;
}

__global__ void __launch_bounds__(256) k_gemm(const float* __restrict__ A,
                                              const float* __restrict__ W,
                                              __half* __restrict__ Ch) {
    __shared__ uint32_t As[128 * AS_STRIDE];
    __shared__ uint32_t Ws[32 * WS_STRIDE];
    int tid = threadIdx.x;
    int lane = tid & 31;
    int w = tid >> 5;
    int warpM = (w >> 1) * 32;
    int warpN = (w & 1) * 64;
    int g = lane >> 2;
    int t = lane & 3;
    int rowBase = blockIdx.x * 128;

    float c[2][8][4];
#pragma unroll
    for (int mi = 0; mi < 2; mi++)
#pragma unroll
        for (int nt = 0; nt < 8; nt++)
#pragma unroll
            for (int q = 0; q < 4; q++) c[mi][nt][q] = 0.f;

    for (int k0 = 0; k0 < 128; k0 += 32) {
#pragma unroll
        for (int i = 0; i < 4; i++) {
            int idx = tid + i * 256;
            int r = idx >> 3;
            int c4 = idx & 7;
            int grow = rowBase + r;
            float4 v = make_float4(0.f, 0.f, 0.f, 0.f);
            if (grow < N_NODES)
                v = *reinterpret_cast<const float4*>(&A[grow * D + k0 + c4 * 4]);
            uint32_t* p = &As[r * AS_STRIDE + c4 * 4];
            p[0] = f2tf32(v.x); p[1] = f2tf32(v.y);
            p[2] = f2tf32(v.z); p[3] = f2tf32(v.w);
        }
#pragma unroll
        for (int i = 0; i < 4; i++) {
            int idx = tid + i * 256;
            int r = idx >> 5;
            int c4 = idx & 31;
            float4 v = *reinterpret_cast<const float4*>(&W[(k0 + r) * D + c4 * 4]);
            uint32_t* p = &Ws[r * WS_STRIDE + c4 * 4];
            p[0] = f2tf32(v.x); p[1] = f2tf32(v.y);
            p[2] = f2tf32(v.z); p[3] = f2tf32(v.w);
        }
        __syncthreads();

#pragma unroll
        for (int kk = 0; kk < 4; kk++) {
            int kb = kk * 8;
            uint32_t af[2][4];
#pragma unroll
            for (int mi = 0; mi < 2; mi++) {
                int r = warpM + mi * 16;
                af[mi][0] = As[(r + g)     * AS_STRIDE + kb + t];
                af[mi][1] = As[(r + g + 8) * AS_STRIDE + kb + t];
                af[mi][2] = As[(r + g)     * AS_STRIDE + kb + t + 4];
                af[mi][3] = As[(r + g + 8) * AS_STRIDE + kb + t + 4];
            }
#pragma unroll
            for (int nt = 0; nt < 8; nt++) {
                int nb = warpN + nt * 8;
                uint32_t b0 = Ws[(kb + t)     * WS_STRIDE + nb + g];
                uint32_t b1 = Ws[(kb + t + 4) * WS_STRIDE + nb + g];
#pragma unroll
                for (int mi = 0; mi < 2; mi++) {
                    asm volatile(
                        "mma.sync.aligned.m16n8k8.row.col.f32.tf32.tf32.f32 "
                        "{%0,%1,%2,%3}, {%4,%5,%6,%7}, {%8,%9}, {%0,%1,%2,%3};"
                        : "+f"(c[mi][nt][0]), "+f"(c[mi][nt][1]),
                          "+f"(c[mi][nt][2]), "+f"(c[mi][nt][3])
                        : "r"(af[mi][0]), "r"(af[mi][1]), "r"(af[mi][2]), "r"(af[mi][3]),
                          "r"(b0), "r"(b1));
                }
            }
        }
        __syncthreads();
    }

    __half2* Ch2 = reinterpret_cast<__half2*>(Ch);
#pragma unroll
    for (int mi = 0; mi < 2; mi++) {
        int r0 = rowBase + warpM + mi * 16 + g;
        int r1 = r0 + 8;
        float d0 = (r0 < N_NODES) ? __ldg(&g_dinv[r0]) : 0.f;
        float d1 = (r1 < N_NODES) ? __ldg(&g_dinv[r1]) : 0.f;
#pragma unroll
        for (int nt = 0; nt < 8; nt++) {
            int colBase = warpN + nt * 8 + t * 2;
            if (r0 < N_NODES)
                Ch2[r0 * 64 + (colBase >> 1)] =
                    __floats2half2_rn(c[mi][nt][0] * d0, c[mi][nt][1] * d0);
            if (r1 < N_NODES)
                Ch2[r1 * 64 + (colBase >> 1)] =
                    __floats2half2_rn(c[mi][nt][2] * d1, c[mi][nt][3] * d1);
        }
    }
}

// ---------------- fused gather + self-loop + bias + LN + ReLU ----------------
__global__ void __launch_bounds__(256) k_gather(const __half* __restrict__ h,
                                                const float* __restrict__ bias,
                                                const float* __restrict__ lng,
                                                const float* __restrict__ lnb,
                                                float* __restrict__ out) {
    int node = blockIdx.x * 8 + (threadIdx.x >> 5);
    if (node >= N_NODES) return;
    int lane = threadIdx.x & 31;
    float di = g_dinv[node];
    const uint2* __restrict__ hu = reinterpret_cast<const uint2*>(h);
    int base = node * 32 + lane;

    uint2 su = __ldg(&hu[base]);
    float2 sf0 = __half22float2(*reinterpret_cast<__half2*>(&su.x));
    float2 sf1 = __half22float2(*reinterpret_cast<__half2*>(&su.y));
    float a0x = sf0.x, a0y = sf0.y, a0z = sf1.x, a0w = sf1.y;
    float a1x = 0.f, a1y = 0.f, a1z = 0.f, a1w = 0.f;

    int beg = __ldg(&g_offs[node]);
    int end = __ldg(&g_offs[node + 1]);
    for (int j0 = beg; j0 < end; j0 += 32) {
        int rem = end - j0;
        int n = rem < 32 ? rem : 32;
        int myidx = 0;
        if (lane < n) myidx = __ldg(&g_adj[j0 + lane]);
        int jj = 0;
#pragma unroll 4
        for (; jj + 2 <= n; jj += 2) {
            int s0 = __shfl_sync(0xFFFFFFFFu, myidx, jj);
            int s1 = __shfl_sync(0xFFFFFFFFu, myidx, jj + 1);
            uint2 u0 = __ldg(&hu[s0 * 32 + lane]);
            uint2 u1 = __ldg(&hu[s1 * 32 + lane]);
            float2 f00 = __half22float2(*reinterpret_cast<__half2*>(&u0.x));
            float2 f01 = __half22float2(*reinterpret_cast<__half2*>(&u0.y));
            float2 f10 = __half22float2(*reinterpret_cast<__half2*>(&u1.x));
            float2 f11 = __half22float2(*reinterpret_cast<__half2*>(&u1.y));
            a0x += f00.x; a1x += f10.x;
            a0y += f00.y; a1y += f10.y;
            a0z += f01.x; a1z += f11.x;
            a0w += f01.y; a1w += f11.y;
        }
        if (jj < n) {
            int s0 = __shfl_sync(0xFFFFFFFFu, myidx, jj);
            uint2 u0 = __ldg(&hu[s0 * 32 + lane]);
            float2 f00 = __half22float2(*reinterpret_cast<__half2*>(&u0.x));
            float2 f01 = __half22float2(*reinterpret_cast<__half2*>(&u0.y));
            a0x += f00.x; a0y += f00.y; a0z += f01.x; a0w += f01.y;
        }
    }

    float4 b4 = __ldg(&reinterpret_cast<const float4*>(bias)[lane]);
    float ax = (a0x + a1x) * di + b4.x;
    float ay = (a0y + a1y) * di + b4.y;
    float az = (a0z + a1z) * di + b4.z;
    float aw = (a0w + a1w) * di + b4.w;

    float s = ax + ay + az + aw;
#pragma unroll
    for (int o = 16; o > 0; o >>= 1) s += __shfl_xor_sync(0xFFFFFFFFu, s, o);
    float mu = s * (1.0f / D);
    float dx = ax - mu, dy = ay - mu, dz = az - mu, dw = aw - mu;
    float sq = dx * dx + dy * dy + dz * dz + dw * dw;
#pragma unroll
    for (int o = 16; o > 0; o >>= 1) sq += __shfl_xor_sync(0xFFFFFFFFu, sq, o);
    float rs = rsqrtf(sq * (1.0f / D) + LN_EPS);

    float4 g4 = __ldg(&reinterpret_cast<const float4*>(lng)[lane]);
    float4 p4 = __ldg(&reinterpret_cast<const float4*>(lnb)[lane]);
    float4 o4;
    o4.x = fmaxf(dx * rs * g4.x + p4.x, 0.f);
    o4.y = fmaxf(dy * rs * g4.y + p4.y, 0.f);
    o4.z = fmaxf(dz * rs * g4.z + p4.z, 0.f);
    o4.w = fmaxf(dw * rs * g4.w + p4.w, 0.f);
    reinterpret_cast<float4*>(out)[node * 32 + lane] = o4;
}

// ---------------- graph mean pool (batch sorted; node-count fused in) ----------------
#define POOL_CHUNK 128
__global__ void __launch_bounds__(128) k_pool(const float* __restrict__ h,
                                              const int* __restrict__ batch) {
    int f = threadIdx.x;
    int start = blockIdx.x * POOL_CHUNK;
    if (start >= N_NODES) return;
    int end = min(start + POOL_CHUNK, N_NODES);
    float sum = 0.f;
    int cnt = 0;
    int cur = __ldg(&batch[start]);
    for (int n = start; n < end; n++) {
        int gg = __ldg(&batch[n]);
        if (gg != cur) {
            atomicAdd(&g_pooled[cur * D + f], sum);
            if (f == 0) atomicAdd(&g_gcnt[cur], (float)cnt);
            sum = 0.f;
            cnt = 0;
            cur = gg;
        }
        sum += h[n * D + f];
        cnt++;
    }
    atomicAdd(&g_pooled[cur * D + f], sum);
    if (f == 0) atomicAdd(&g_gcnt[cur], (float)cnt);
}

// ---------------- head ----------------
__global__ void __launch_bounds__(1024) k_final(const float* __restrict__ lw,
                                                const float* __restrict__ lb,
                                                float* __restrict__ out) {
    int t = threadIdx.x;
    int g = t >> 4;
    int o = t & 15;
    float acc = 0.f;
#pragma unroll 8
    for (int f = 0; f < D; f++) acc += g_pooled[g * D + f] * __ldg(&lw[f * DOUT + o]);
    out[t] = acc / fmaxf(g_gcnt[g], 1.0f) + __ldg(&lb[o]);
}

// ---------------- launch (fork-join: CSR build overlaps GEMM1) ----------------
extern "C" void kernel_launch(void* const* d_in, const int* in_sizes, int n_in,
                              void* d_out, int out_size) {
    const float* x     = (const float*)d_in[0];
    const int*   ei    = (const int*)d_in[1];
    const int*   src   = ei;
    const int*   dst   = ei + N_EDGES;
    const int*   batch = (const int*)d_in[2];
    const float* W1    = (const float*)d_in[3];
    const float* b1    = (const float*)d_in[4];
    const float* W2    = (const float*)d_in[5];
    const float* b2    = (const float*)d_in[6];
    const float* lng   = (const float*)d_in[7];
    const float* lnb   = (const float*)d_in[8];
    const float* lw    = (const float*)d_in[9];
    const float* lbias = (const float*)d_in[10];
    float* out = (float*)d_out;

    __half* pAh = nullptr;
    float*  pB  = nullptr;
    cudaGetSymbolAddress((void**)&pAh, g_Ah);
    cudaGetSymbolAddress((void**)&pB, g_B);

    // side stream + events, created once on the first (non-capturing) call
    static cudaStream_t s_side = nullptr;
    static cudaEvent_t  s_evFork = nullptr, s_evJoin = nullptr;
    if (!s_side) {
        cudaStreamCreateWithFlags(&s_side, cudaStreamNonBlocking);
        cudaEventCreateWithFlags(&s_evFork, cudaEventDisableTiming);
        cudaEventCreateWithFlags(&s_evJoin, cudaEventDisableTiming);
    }
    cudaStream_t s0 = 0;   // harness capture stream (legacy default)

    const int T = 256;
    // prologue: counts + dinv (needed by both branches)
    k_init<<<(N_NODES + T - 1) / T, T, 0, s0>>>();
    k_count<<<(N_EDGES + T - 1) / T, T, 0, s0>>>(dst);
    k_dinv<<<(N_NODES + T - 1) / T, T, 0, s0>>>();

    // fork: side stream builds CSR while main stream runs GEMM1
    cudaEventRecord(s_evFork, s0);
    cudaStreamWaitEvent(s_side, s_evFork, 0);
    k_scan1<<<SCAN_NB, SCAN_B, 0, s_side>>>();
    k_scan2<<<1, 128, 0, s_side>>>();
    k_scan3<<<SCAN_NB, SCAN_B, 0, s_side>>>();
    k_fill<<<(N_EDGES + T - 1) / T, T, 0, s_side>>>(src, dst);
    cudaEventRecord(s_evJoin, s_side);

    k_gemm<<<(N_NODES + 127) / 128, 256, 0, s0>>>(x, W1, pAh);

    // join: gather1 needs both GEMM1 output and the CSR
    cudaStreamWaitEvent(s0, s_evJoin, 0);
    k_gather<<<(N_NODES + 7) / 8, 256, 0, s0>>>(pAh, b1, lng, lnb, pB);

    // layer 2
    k_gemm<<<(N_NODES + 127) / 128, 256, 0, s0>>>(pB, W2, pAh);
    k_gather<<<(N_NODES + 7) / 8, 256, 0, s0>>>(pAh, b2, lng, lnb, pB);

    // pool + head
    k_pool<<<(N_NODES + POOL_CHUNK - 1) / POOL_CHUNK, 128, 0, s0>>>(pB, batch);
    k_final<<<1, 1024, 0, s0>>>(lw, lbias, out);
}